// round 14
// baseline (speedup 1.0000x reference)
#include <cuda_runtime.h>
#include <cuda_fp16.h>
#include <cstdint>

#define NB    16
#define SEQ   512
#define MTOK  8192
#define EDIM  768
#define HDIM  1024
#define NLANG 5

// ---------------- scratch (static device globals; allocation-free) ----------------
__device__ __align__(128) __half d_nerH [MTOK*EDIM];          // fp16 features [m][k]
__device__ __align__(128) __half d_topH [MTOK*EDIM];
__device__ __align__(128) __half d_WnerH[EDIM*HDIM];          // W fp16, native [k][n]
__device__ __align__(128) __half d_WtopH[EDIM*HDIM];
__device__ __align__(128) __half d_Wg1H [NLANG*2*HDIM*HDIM];  // Wg1 fp16 [l][k=2H][n=H]
__device__ __align__(128) __half d_actH [MTOK*2*HDIM];        // [ner | top] LN'd fp16
__device__ __align__(128) __half d_preN [MTOK*HDIM];          // pre-LN fp16 (GEMM1 out)
__device__ __align__(128) __half d_preT [MTOK*HDIM];
__device__ __align__(128) __half d_hidH [MTOK*HDIM];          // gate hidden fp16
__device__ int   d_lang[NB];

// ---------------- PTX helpers ----------------
__device__ __forceinline__ uint32_t smem_u32(const void* p) {
    uint32_t a;
    asm("{ .reg .u64 t; cvta.to.shared.u64 t, %1; cvt.u32.u64 %0, t; }" : "=r"(a) : "l"(p));
    return a;
}
#define CP16(dst, src) asm volatile("cp.async.cg.shared.global [%0], [%1], 16;\n"::"r"(dst),"l"(src))
#define CP_COMMIT()    asm volatile("cp.async.commit_group;\n")
#define CP_WAIT(n)     asm volatile("cp.async.wait_group %0;\n"::"n"(n))

#define LDSM4(r, a) \
    asm volatile("ldmatrix.sync.aligned.m8n8.x4.shared.b16 {%0,%1,%2,%3}, [%4];" \
        : "=r"((r)[0]), "=r"((r)[1]), "=r"((r)[2]), "=r"((r)[3]) : "r"(a))
#define LDSM4T(r, a) \
    asm volatile("ldmatrix.sync.aligned.m8n8.x4.trans.shared.b16 {%0,%1,%2,%3}, [%4];" \
        : "=r"((r)[0]), "=r"((r)[1]), "=r"((r)[2]), "=r"((r)[3]) : "r"(a))

#define MMA16816(d, a, b) \
    asm volatile("mma.sync.aligned.m16n8k16.row.col.f32.f16.f16.f32 " \
        "{%0,%1,%2,%3}, {%4,%5,%6,%7}, {%8,%9}, {%0,%1,%2,%3};" \
        : "+f"((d)[0]), "+f"((d)[1]), "+f"((d)[2]), "+f"((d)[3]) \
        : "r"((a)[0]), "r"((a)[1]), "r"((a)[2]), "r"((a)[3]), "r"((b)[0]), "r"((b)[1]))

// smem tiles (bytes): A [128 m][72 halfs] pitch 144B; B [64 k][136 halfs] pitch 272B
#define APITCH   144
#define BPITCH   272
#define A_TILE   (128*APITCH)
#define B_TILE   (64*BPITCH)
#define STAGE    (A_TILE + B_TILE)         // 35840
#define NSTAGE   3
#define SM_A(s)  ((s)*STAGE)
#define SM_B(s)  ((s)*STAGE + A_TILE)
#define SMEM_MM  (NSTAGE*STAGE)            // 107520 -> 2 CTAs/SM

#define YMAIN    64                         // GEMM rows of the grid
#define YCONV    16                         // converter rows (x8 = 128 conv CTAs)
#define NCONV    (YCONV*8*256)              // converter thread count

// region sizes in float4 granules
#define R_FEAT  (MTOK*EDIM/4)
#define R_WSH   (EDIM*HDIM/4)
#define R_WG1   (NLANG*2*HDIM*HDIM/4)
#define R_WG1A  (R_WG1/2)
#define R_WG1B  (R_WG1 - R_WG1A)

// ---------------- warp reduction ----------------
__device__ __forceinline__ float warpSum(float v) {
    #pragma unroll
    for (int o = 16; o > 0; o >>= 1) v += __shfl_xor_sync(0xffffffffu, v, o);
    return v;
}

__device__ __forceinline__ void cvt_region(
    const float* __restrict__ src, __half* __restrict__ dst, int n4, int t0, int stride)
{
    for (int i = t0; i < n4; i += stride) {
        float4 v = ((const float4*)src)[i];
        __half2* d2 = (__half2*)(dst + (size_t)i * 4);
        d2[0] = __floats2half2_rn(v.x, v.y);
        d2[1] = __floats2half2_rn(v.z, v.w);
    }
}

// ---------------- prep0: decode + convert ner features + W_ner (serial prefix) ------
#define PREP0_N (R_FEAT + R_WSH)
#define PREP0_GRID ((PREP0_N + 1023) / 1024)
__global__ void __launch_bounds__(256) k_prep0(
    const float* __restrict__ ner, const float* __restrict__ Wner, const int* __restrict__ lp)
{
    int gid = blockIdx.x * blockDim.x + threadIdx.x;
    if (gid == 0) {
        int m = 0;
        #pragma unroll
        for (int j = 1; j < 16; j += 2) m |= lp[j];
        bool is64 = (m == 0);
        for (int b = 0; b < NB; b++) d_lang[b] = is64 ? lp[2*b] : lp[b];
    }
    int stride = PREP0_GRID * 256;
    cvt_region(ner,  d_nerH,  R_FEAT, gid, stride);
    cvt_region(Wner, d_WnerH, R_WSH,  gid, stride);
}

// ---------------- fp16 GEMM: C[128 m, 128 n] tile; 8 warps, warp tile 32x64 -----------
// CONV: grid.y in [YMAIN, YMAIN+YCONV) -> converter CTAs (fp32->fp16, up to 3 regions).
template<int NK, bool GATE, bool CONV>
__global__ void __launch_bounds__(256, 2) k_mm_fp16(
    const __half* __restrict__ A0, const __half* __restrict__ W0,
    const float* __restrict__ bias0, __half* __restrict__ C,
    const float* __restrict__ c0, __half* __restrict__ e0, int n0,
    const float* __restrict__ c1, __half* __restrict__ e1, int n1,
    const float* __restrict__ c2, __half* __restrict__ e2, int n2)
{
    constexpr int K = NK * 64;
    if (CONV && blockIdx.y >= YMAIN) {
        int t0 = ((blockIdx.y - YMAIN) * gridDim.x + blockIdx.x) * 256 + threadIdx.x;
        if (n0) cvt_region(c0, e0, n0, t0, NCONV);
        if (n1) cvt_region(c1, e1, n1, t0, NCONV);
        if (n2) cvt_region(c2, e2, n2, t0, NCONV);
        return;
    }
    extern __shared__ __align__(128) char smem[];
    const uint32_t sb = smem_u32(smem);
    const int tid = threadIdx.x, wid = tid >> 5, l = tid & 31;
    const int m0 = blockIdx.y * 128, n0b = blockIdx.x * 128;
    const int wm = (wid & 3) * 32, wn = (wid >> 2) * 64;

    const __half* Ah = A0;
    const __half* Wt = W0;
    const float*  bias = bias0;
    if (GATE) {
        int lang = d_lang[blockIdx.y >> 2];
        Wt   = W0 + (size_t)lang * (2*HDIM) * HDIM;
        bias = bias0 + lang * HDIM;
    }

    const uint32_t laneA = (uint32_t)((l & 15) * APITCH + (l >> 4) * 16);
    const uint32_t laneB = (uint32_t)((l & 15) * BPITCH + (l >> 4) * 16);

    auto loadT = [&](int it, int stage) {
        const int kc = it * 64;
        const uint32_t aB = sb + SM_A(stage);
        const uint32_t bB = sb + SM_B(stage);
        #pragma unroll
        for (int i = 0; i < 4; i++) {          // A: 128 rows x 8 x 16B
            int idx = tid + i * 256;
            int r = idx >> 3, c = idx & 7;
            CP16(aB + r * APITCH + c * 16, Ah + (size_t)(m0 + r) * K + kc + c * 8);
        }
        #pragma unroll
        for (int i = 0; i < 4; i++) {          // B: 64 rows x 16 x 16B
            int idx = tid + i * 256;
            int r = idx >> 4, c = idx & 15;
            CP16(bB + r * BPITCH + c * 16, Wt + (size_t)(kc + r) * HDIM + n0b + c * 8);
        }
    };

    float acc[2][8][4] = {};

    loadT(0, 0); CP_COMMIT();
    loadT(1, 1); CP_COMMIT();

    int stage = 0;
    int nstage = 2 % NSTAGE;
    for (int it = 0; it < NK; it++) {
        CP_WAIT(1);
        __syncthreads();
        if (it + 2 < NK) loadT(it + 2, nstage);
        CP_COMMIT();

        const uint32_t aBase = sb + SM_A(stage) + (uint32_t)(wm * APITCH) + laneA;
        const uint32_t bBase = sb + SM_B(stage) + (uint32_t)(wn * 2) + laneB;
        #pragma unroll
        for (int ks = 0; ks < 4; ks++) {
            uint32_t af[2][4], bf[8][2];
            #pragma unroll
            for (int mt = 0; mt < 2; mt++)
                LDSM4(af[mt], aBase + mt * (16 * APITCH) + ks * 32);
            #pragma unroll
            for (int j = 0; j < 4; j++) {
                uint32_t t4[4];
                LDSM4T(t4, bBase + ks * (16 * BPITCH) + j * 32);
                bf[2*j][0] = t4[0]; bf[2*j][1] = t4[1];
                bf[2*j+1][0] = t4[2]; bf[2*j+1][1] = t4[3];
            }
            #pragma unroll
            for (int mt = 0; mt < 2; mt++)
                #pragma unroll
                for (int nt = 0; nt < 8; nt++)
                    MMA16816(acc[mt][nt], af[mt], bf[nt]);
        }
        stage  = (stage  + 1 == NSTAGE) ? 0 : stage + 1;
        nstage = (nstage + 1 == NSTAGE) ? 0 : nstage + 1;
    }

    // epilogue: + bias (fp32), store fp16
    #pragma unroll
    for (int mt = 0; mt < 2; mt++) {
        int r0 = m0 + wm + mt * 16 + (l >> 2);
        #pragma unroll
        for (int nt = 0; nt < 8; nt++) {
            int c = n0b + wn + nt * 8 + 2 * (l & 3);
            float bv0 = bias[c], bv1 = bias[c + 1];
            *(__half2*)(C + (size_t)r0 * HDIM + c) =
                __floats2half2_rn(acc[mt][nt][0] + bv0, acc[mt][nt][1] + bv1);
            *(__half2*)(C + (size_t)(r0 + 8) * HDIM + c) =
                __floats2half2_rn(acc[mt][nt][2] + bv0, acc[mt][nt][3] + bv1);
        }
    }
}

// ---------------- unpack helper: uint4 (8 halfs) -> 8 floats ----------------
__device__ __forceinline__ void unpack8(const uint4& r, float* f) {
    float2 p;
    p = __half22float2(*(const __half2*)&r.x); f[0] = p.x; f[1] = p.y;
    p = __half22float2(*(const __half2*)&r.y); f[2] = p.x; f[3] = p.y;
    p = __half22float2(*(const __half2*)&r.z); f[4] = p.x; f[5] = p.y;
    p = __half22float2(*(const __half2*)&r.w); f[6] = p.x; f[7] = p.y;
}

// ---------------- LN + ReLU: warp-per-row, fp16 in (pre) / fp16 out (actH) ----------------
__global__ void __launch_bounds__(256) k_ln_relu2(
    const float* __restrict__ gN, const float* __restrict__ bN,
    const float* __restrict__ gT, const float* __restrict__ bT)
{
    const int w = threadIdx.x >> 5, l = threadIdx.x & 31;
    const int row0 = blockIdx.x * 8 + w;
    const __half *src; const float *gamma, *beta; int hoff, row;
    if (row0 < MTOK) { src = d_preN; gamma = gN; beta = bN; hoff = 0;    row = row0; }
    else             { src = d_preT; gamma = gT; beta = bT; hoff = HDIM; row = row0 - MTOK; }
    const uint4* x = (const uint4*)(src + (size_t)row * HDIM);
    float f[4][8];
    float s = 0.f;
    #pragma unroll
    for (int i = 0; i < 4; i++) {
        uint4 raw = x[i*32 + l];
        unpack8(raw, f[i]);
        #pragma unroll
        for (int j = 0; j < 8; j++) s += f[i][j];
    }
    s = warpSum(s);
    float mu = s * (1.f / HDIM);
    float sq = 0.f;
    #pragma unroll
    for (int i = 0; i < 4; i++)
        #pragma unroll
        for (int j = 0; j < 8; j++) { float d = f[i][j] - mu; sq += d*d; }
    sq = warpSum(sq);
    float inv = rsqrtf(sq * (1.f / HDIM) + 1e-5f);
    uint4* dh = (uint4*)(d_actH + (size_t)row * (2*HDIM) + hoff);
    const float4* g4 = (const float4*)gamma;
    const float4* b4 = (const float4*)beta;
    #pragma unroll
    for (int i = 0; i < 4; i++) {
        int e = (i*32 + l) * 2;
        float o[8];
        #pragma unroll
        for (int h = 0; h < 2; h++) {
            float4 g = g4[e + h], b = b4[e + h];
            o[h*4+0] = fmaxf((f[i][h*4+0]-mu)*inv*g.x + b.x, 0.f);
            o[h*4+1] = fmaxf((f[i][h*4+1]-mu)*inv*g.y + b.y, 0.f);
            o[h*4+2] = fmaxf((f[i][h*4+2]-mu)*inv*g.z + b.z, 0.f);
            o[h*4+3] = fmaxf((f[i][h*4+3]-mu)*inv*g.w + b.w, 0.f);
        }
        uint4 ov;
        *(__half2*)&ov.x = __floats2half2_rn(o[0], o[1]);
        *(__half2*)&ov.y = __floats2half2_rn(o[2], o[3]);
        *(__half2*)&ov.z = __floats2half2_rn(o[4], o[5]);
        *(__half2*)&ov.w = __floats2half2_rn(o[6], o[7]);
        dh[i*32 + l] = ov;
    }
}

// ---------------- final: warp-per-row. LN+ReLU(hidH fp16)->Wg2->sigmoid->gate actH ----
__global__ void __launch_bounds__(256) k_gate_finish(
    const float* __restrict__ gg, const float* __restrict__ bgv,
    const float* __restrict__ Wg2, const float* __restrict__ bg2,
    float* __restrict__ out)
{
    const int w = threadIdx.x >> 5, l = threadIdx.x & 31;
    const int row  = blockIdx.x * 8 + w;
    const int lang = d_lang[row >> 9];
    const uint4* x = (const uint4*)(d_hidH + (size_t)row * HDIM);
    float f[4][8];
    float s = 0.f;
    #pragma unroll
    for (int i = 0; i < 4; i++) {
        uint4 raw = x[i*32 + l];
        unpack8(raw, f[i]);
        #pragma unroll
        for (int j = 0; j < 8; j++) s += f[i][j];
    }
    s = warpSum(s);
    float mu = s * (1.f / HDIM);
    float sq = 0.f;
    #pragma unroll
    for (int i = 0; i < 4; i++)
        #pragma unroll
        for (int j = 0; j < 8; j++) { float d = f[i][j] - mu; sq += d*d; }
    sq = warpSum(sq);
    float inv = rsqrtf(sq * (1.f / HDIM) + 1e-5f);

    const float4* g4 = (const float4*)(gg  + (size_t)lang * HDIM);
    const float4* b4 = (const float4*)(bgv + (size_t)lang * HDIM);
    const float4* w4 = (const float4*)(Wg2 + (size_t)lang * HDIM * 2);
    float s0 = 0.f, s1 = 0.f;
    #pragma unroll
    for (int i = 0; i < 4; i++) {
        int e = (i*32 + l) * 2;
        #pragma unroll
        for (int h = 0; h < 2; h++) {
            float4 g = g4[e + h], b = b4[e + h];
            float h0 = fmaxf((f[i][h*4+0]-mu)*inv*g.x + b.x, 0.f);
            float h1 = fmaxf((f[i][h*4+1]-mu)*inv*g.y + b.y, 0.f);
            float h2 = fmaxf((f[i][h*4+2]-mu)*inv*g.z + b.z, 0.f);
            float h3 = fmaxf((f[i][h*4+3]-mu)*inv*g.w + b.w, 0.f);
            float4 wa = w4[(e + h)*2], wb = w4[(e + h)*2 + 1];
            s0 += h0*wa.x + h1*wa.z + h2*wb.x + h3*wb.z;
            s1 += h0*wa.y + h1*wa.w + h2*wb.y + h3*wb.w;
        }
    }
    s0 = warpSum(s0);
    s1 = warpSum(s1);
    float g0 = 1.f / (1.f + expf(-(s0 + bg2[lang*2 + 0])));
    float g1 = 1.f / (1.f + expf(-(s1 + bg2[lang*2 + 1])));

    const uint4* an = (const uint4*)(d_actH + (size_t)row * (2*HDIM));
    const uint4* at = (const uint4*)(d_actH + (size_t)row * (2*HDIM) + HDIM);
    float4* o0 = (float4*)(out + (size_t)row * HDIM);
    float4* o1 = (float4*)(out + (size_t)MTOK * HDIM + (size_t)row * HDIM);
    #pragma unroll
    for (int i = 0; i < 4; i++) {
        int idx = i*32 + l;
        float na[8], ta[8];
        unpack8(an[idx], na);
        unpack8(at[idx], ta);
        o0[idx*2]   = make_float4(na[0]*g0, na[1]*g0, na[2]*g0, na[3]*g0);
        o0[idx*2+1] = make_float4(na[4]*g0, na[5]*g0, na[6]*g0, na[7]*g0);
        o1[idx*2]   = make_float4(ta[0]*g1, ta[1]*g1, ta[2]*g1, ta[3]*g1);
        o1[idx*2+1] = make_float4(ta[4]*g1, ta[5]*g1, ta[6]*g1, ta[7]*g1);
    }
}

extern "C" void kernel_launch(void* const* d_in, const int* in_sizes, int n_in,
                              void* d_out, int out_size)
{
    const float* ner    = (const float*)d_in[0];
    const float* topf   = (const float*)d_in[1];
    const int*   lang   = (const int*)d_in[2];
    const float* W_ner  = (const float*)d_in[3];
    const float* b_ner  = (const float*)d_in[4];
    const float* g_ner  = (const float*)d_in[5];
    const float* be_ner = (const float*)d_in[6];
    const float* W_top  = (const float*)d_in[7];
    const float* b_top  = (const float*)d_in[8];
    const float* g_top  = (const float*)d_in[9];
    const float* be_top = (const float*)d_in[10];
    const float* Wg1    = (const float*)d_in[11];
    const float* bg1    = (const float*)d_in[12];
    const float* gg     = (const float*)d_in[13];
    const float* bg     = (const float*)d_in[14];
    const float* Wg2    = (const float*)d_in[15];
    const float* bg2    = (const float*)d_in[16];
    float* out = (float*)d_out;

    __half *pNerH, *pTopH, *pWner, *pWtop, *pWg1, *pActH, *pPreN, *pPreT, *pHidH;
    cudaGetSymbolAddress((void**)&pNerH, d_nerH);
    cudaGetSymbolAddress((void**)&pTopH, d_topH);
    cudaGetSymbolAddress((void**)&pWner, d_WnerH);
    cudaGetSymbolAddress((void**)&pWtop, d_WtopH);
    cudaGetSymbolAddress((void**)&pWg1,  d_Wg1H);
    cudaGetSymbolAddress((void**)&pActH, d_actH);
    cudaGetSymbolAddress((void**)&pPreN, d_preN);
    cudaGetSymbolAddress((void**)&pPreT, d_preT);
    cudaGetSymbolAddress((void**)&pHidH, d_hidH);

    static bool attr_done = false;
    if (!attr_done) {
        cudaFuncSetAttribute(k_mm_fp16<12,false,true>, cudaFuncAttributeMaxDynamicSharedMemorySize, SMEM_MM);
        cudaFuncSetAttribute(k_mm_fp16<32,true,false>, cudaFuncAttributeMaxDynamicSharedMemorySize, SMEM_MM);
        attr_done = true;
    }

    // serial prefix: decode + convert ner features + W_ner
    k_prep0<<<PREP0_GRID, 256>>>(ner, W_ner, lang);

    // GEMM1-ner + converter CTAs (topf, W_top, Wg1 first half)
    k_mm_fp16<12,false,true><<<dim3(HDIM/128, YMAIN + YCONV), 256, SMEM_MM>>>(
        pNerH, pWner, b_ner, pPreN,
        topf,  pTopH, R_FEAT,
        W_top, pWtop, R_WSH,
        Wg1,   pWg1,  R_WG1A);

    // GEMM1-top + converter CTAs (Wg1 second half)
    k_mm_fp16<12,false,true><<<dim3(HDIM/128, YMAIN + YCONV), 256, SMEM_MM>>>(
        pTopH, pWtop, b_top, pPreT,
        Wg1 + (size_t)R_WG1A * 4, pWg1 + (size_t)R_WG1A * 4, R_WG1B,
        nullptr, nullptr, 0,
        nullptr, nullptr, 0);

    k_ln_relu2<<<2*MTOK/8, 256>>>(g_ner, be_ner, g_top, be_top);

    // gate MLP (K=2048), per-batch language selected
    k_mm_fp16<32,true,false><<<dim3(HDIM/128, YMAIN), 256, SMEM_MM>>>(
        pActH, pWg1, bg1, pHidH,
        nullptr, nullptr, 0, nullptr, nullptr, 0, nullptr, nullptr, 0);

    k_gate_finish<<<MTOK/8, 256>>>(gg, bg, Wg2, bg2, out);
}

// round 15
// speedup vs baseline: 1.0518x; 1.0518x over previous
#include <cuda_runtime.h>
#include <cuda_fp16.h>
#include <cstdint>

#define NB    16
#define SEQ   512
#define MTOK  8192
#define EDIM  768
#define HDIM  1024
#define NLANG 5

// ---------------- scratch (static device globals; allocation-free) ----------------
__device__ __align__(128) __half d_nerH [MTOK*EDIM];          // fp16 features [m][k]
__device__ __align__(128) __half d_topH [MTOK*EDIM];
__device__ __align__(128) __half d_WnerH[EDIM*HDIM];          // W fp16, native [k][n]
__device__ __align__(128) __half d_WtopH[EDIM*HDIM];
__device__ __align__(128) __half d_Wg1H [NLANG*2*HDIM*HDIM];  // Wg1 fp16 [l][k=2H][n=H]
__device__ __align__(128) __half d_actH [MTOK*2*HDIM];        // [ner | top] LN'd fp16
__device__ __align__(128) __half d_preN [MTOK*HDIM];          // pre-LN fp16 (GEMM1 out)
__device__ __align__(128) __half d_preT [MTOK*HDIM];
__device__ __align__(128) __half d_hidH [MTOK*HDIM];          // gate hidden fp16
__device__ int   d_lang[NB];

// ---------------- PTX helpers ----------------
__device__ __forceinline__ uint32_t smem_u32(const void* p) {
    uint32_t a;
    asm("{ .reg .u64 t; cvta.to.shared.u64 t, %1; cvt.u32.u64 %0, t; }" : "=r"(a) : "l"(p));
    return a;
}
#define CP16(dst, src) asm volatile("cp.async.cg.shared.global [%0], [%1], 16;\n"::"r"(dst),"l"(src))
#define CP_COMMIT()    asm volatile("cp.async.commit_group;\n")
#define CP_WAIT(n)     asm volatile("cp.async.wait_group %0;\n"::"n"(n))

#define LDSM4(r, a) \
    asm volatile("ldmatrix.sync.aligned.m8n8.x4.shared.b16 {%0,%1,%2,%3}, [%4];" \
        : "=r"((r)[0]), "=r"((r)[1]), "=r"((r)[2]), "=r"((r)[3]) : "r"(a))
#define LDSM4T(r, a) \
    asm volatile("ldmatrix.sync.aligned.m8n8.x4.trans.shared.b16 {%0,%1,%2,%3}, [%4];" \
        : "=r"((r)[0]), "=r"((r)[1]), "=r"((r)[2]), "=r"((r)[3]) : "r"(a))

#define MMA16816(d, a, b) \
    asm volatile("mma.sync.aligned.m16n8k16.row.col.f32.f16.f16.f32 " \
        "{%0,%1,%2,%3}, {%4,%5,%6,%7}, {%8,%9}, {%0,%1,%2,%3};" \
        : "+f"((d)[0]), "+f"((d)[1]), "+f"((d)[2]), "+f"((d)[3]) \
        : "r"((a)[0]), "r"((a)[1]), "r"((a)[2]), "r"((a)[3]), "r"((b)[0]), "r"((b)[1]))

// smem tiles (bytes): A [128 m][72 halfs] pitch 144B; B [64 k][136 halfs] pitch 272B
#define APITCH   144
#define BPITCH   272
#define A_TILE   (128*APITCH)
#define B_TILE   (64*BPITCH)
#define STAGE    (A_TILE + B_TILE)         // 35840
#define NSTAGE   3
#define SM_A(s)  ((s)*STAGE)
#define SM_B(s)  ((s)*STAGE + A_TILE)
#define SMEM_MM  (NSTAGE*STAGE)            // 107520 -> 2 CTAs/SM

#define YMAIN    64                         // GEMM rows of the grid
#define YCONV    16                         // converter rows appended (x8 x2 z = 256 CTAs)
#define NCONVT   (2*YCONV*8*256)            // converter thread count across both z slices

// region sizes in float4 granules
#define R_FEAT  (MTOK*EDIM/4)
#define R_WSH   (EDIM*HDIM/4)
#define R_WG1   (NLANG*2*HDIM*HDIM/4)

// ---------------- warp reduction ----------------
__device__ __forceinline__ float warpSum(float v) {
    #pragma unroll
    for (int o = 16; o > 0; o >>= 1) v += __shfl_xor_sync(0xffffffffu, v, o);
    return v;
}

__device__ __forceinline__ void cvt_region(
    const float* __restrict__ src, __half* __restrict__ dst, int n4, int t0, int stride)
{
    for (int i = t0; i < n4; i += stride) {
        float4 v = ((const float4*)src)[i];
        __half2* d2 = (__half2*)(dst + (size_t)i * 4);
        d2[0] = __floats2half2_rn(v.x, v.y);
        d2[1] = __floats2half2_rn(v.z, v.w);
    }
}

// ---------------- prep0: decode + convert both feature mats + shared weights ----------
#define PREP0_N (2*R_FEAT + 2*R_WSH)
#define PREP0_GRID ((PREP0_N + 1023) / 1024)
__global__ void __launch_bounds__(256) k_prep0(
    const float* __restrict__ ner, const float* __restrict__ topf,
    const float* __restrict__ Wner, const float* __restrict__ Wtop,
    const int* __restrict__ lp)
{
    int gid = blockIdx.x * blockDim.x + threadIdx.x;
    if (gid == 0) {
        int m = 0;
        #pragma unroll
        for (int j = 1; j < 16; j += 2) m |= lp[j];
        bool is64 = (m == 0);
        for (int b = 0; b < NB; b++) d_lang[b] = is64 ? lp[2*b] : lp[b];
    }
    int stride = PREP0_GRID * 256;
    cvt_region(ner,  d_nerH,  R_FEAT, gid, stride);
    cvt_region(topf, d_topH,  R_FEAT, gid, stride);
    cvt_region(Wner, d_WnerH, R_WSH,  gid, stride);
    cvt_region(Wtop, d_WtopH, R_WSH,  gid, stride);
}

// ---------------- fp16 GEMM: C[128 m, 128 n] tile; 8 warps, warp tile 32x64 -----------
// z selects (A,W,bias,C) pair for the shared-transform launch; GATE uses per-language W.
// CONV: grid.y in [YMAIN, YMAIN+YCONV) -> converter CTAs (fp32->fp16 of one region).
template<int NK, bool GATE, bool CONV>
__global__ void __launch_bounds__(256, 2) k_mm_fp16(
    const __half* __restrict__ A0, const __half* __restrict__ A1,
    const __half* __restrict__ W0, const __half* __restrict__ W1,
    const float* __restrict__ bz0, const float* __restrict__ bz1,
    __half* __restrict__ C0, __half* __restrict__ C1,
    const float* __restrict__ csrc, __half* __restrict__ cdst, int cn4)
{
    constexpr int K = NK * 64;
    if (CONV && blockIdx.y >= YMAIN) {
        int t0 = ((blockIdx.z * YCONV + (blockIdx.y - YMAIN)) * gridDim.x + blockIdx.x) * 256
                 + threadIdx.x;
        cvt_region(csrc, cdst, cn4, t0, NCONVT);
        return;
    }
    extern __shared__ __align__(128) char smem[];
    const uint32_t sb = smem_u32(smem);
    const int tid = threadIdx.x, wid = tid >> 5, l = tid & 31;
    const int m0 = blockIdx.y * 128, n0 = blockIdx.x * 128;
    const int wm = (wid & 3) * 32, wn = (wid >> 2) * 64;

    const __half *Ah, *Wt; const float *bias; __half *C;
    if (GATE) {
        int lang = d_lang[blockIdx.y >> 2];
        Ah = A0;
        Wt = W0 + (size_t)lang * (2*HDIM) * HDIM;
        bias = bz0 + lang * HDIM;
        C = C0;
    } else {
        bool z = (blockIdx.z != 0);
        Ah = z ? A1 : A0; Wt = z ? W1 : W0; bias = z ? bz1 : bz0; C = z ? C1 : C0;
    }

    const uint32_t laneA = (uint32_t)((l & 15) * APITCH + (l >> 4) * 16);
    const uint32_t laneB = (uint32_t)((l & 15) * BPITCH + (l >> 4) * 16);

    auto loadT = [&](int it, int stage) {
        const int kc = it * 64;
        const uint32_t aB = sb + SM_A(stage);
        const uint32_t bB = sb + SM_B(stage);
        #pragma unroll
        for (int i = 0; i < 4; i++) {          // A: 128 rows x 8 x 16B
            int idx = tid + i * 256;
            int r = idx >> 3, c = idx & 7;
            CP16(aB + r * APITCH + c * 16, Ah + (size_t)(m0 + r) * K + kc + c * 8);
        }
        #pragma unroll
        for (int i = 0; i < 4; i++) {          // B: 64 rows x 16 x 16B
            int idx = tid + i * 256;
            int r = idx >> 4, c = idx & 15;
            CP16(bB + r * BPITCH + c * 16, Wt + (size_t)(kc + r) * HDIM + n0 + c * 8);
        }
    };

    float acc[2][8][4] = {};

    loadT(0, 0); CP_COMMIT();
    loadT(1, 1); CP_COMMIT();

    int stage = 0;
    int nstage = 2 % NSTAGE;
    for (int it = 0; it < NK; it++) {
        CP_WAIT(1);
        __syncthreads();
        if (it + 2 < NK) loadT(it + 2, nstage);
        CP_COMMIT();

        const uint32_t aBase = sb + SM_A(stage) + (uint32_t)(wm * APITCH) + laneA;
        const uint32_t bBase = sb + SM_B(stage) + (uint32_t)(wn * 2) + laneB;
        #pragma unroll
        for (int ks = 0; ks < 4; ks++) {
            uint32_t af[2][4], bf[8][2];
            #pragma unroll
            for (int mt = 0; mt < 2; mt++)
                LDSM4(af[mt], aBase + mt * (16 * APITCH) + ks * 32);
            #pragma unroll
            for (int j = 0; j < 4; j++) {
                uint32_t t4[4];
                LDSM4T(t4, bBase + ks * (16 * BPITCH) + j * 32);
                bf[2*j][0] = t4[0]; bf[2*j][1] = t4[1];
                bf[2*j+1][0] = t4[2]; bf[2*j+1][1] = t4[3];
            }
            #pragma unroll
            for (int mt = 0; mt < 2; mt++)
                #pragma unroll
                for (int nt = 0; nt < 8; nt++)
                    MMA16816(acc[mt][nt], af[mt], bf[nt]);
        }
        stage  = (stage  + 1 == NSTAGE) ? 0 : stage + 1;
        nstage = (nstage + 1 == NSTAGE) ? 0 : nstage + 1;
    }

    // epilogue: + bias (fp32), store fp16
    #pragma unroll
    for (int mt = 0; mt < 2; mt++) {
        int r0 = m0 + wm + mt * 16 + (l >> 2);
        #pragma unroll
        for (int nt = 0; nt < 8; nt++) {
            int c = n0 + wn + nt * 8 + 2 * (l & 3);
            float bv0 = bias[c], bv1 = bias[c + 1];
            *(__half2*)(C + (size_t)r0 * HDIM + c) =
                __floats2half2_rn(acc[mt][nt][0] + bv0, acc[mt][nt][1] + bv1);
            *(__half2*)(C + (size_t)(r0 + 8) * HDIM + c) =
                __floats2half2_rn(acc[mt][nt][2] + bv0, acc[mt][nt][3] + bv1);
        }
    }
}

// ---------------- unpack helper: uint4 (8 halfs) -> 8 floats ----------------
__device__ __forceinline__ void unpack8(const uint4& r, float* f) {
    float2 p;
    p = __half22float2(*(const __half2*)&r.x); f[0] = p.x; f[1] = p.y;
    p = __half22float2(*(const __half2*)&r.y); f[2] = p.x; f[3] = p.y;
    p = __half22float2(*(const __half2*)&r.z); f[4] = p.x; f[5] = p.y;
    p = __half22float2(*(const __half2*)&r.w); f[6] = p.x; f[7] = p.y;
}

// ---------------- LN + ReLU: warp-per-row, fp16 in (pre) / fp16 out (actH) ----------------
__global__ void __launch_bounds__(256) k_ln_relu2(
    const float* __restrict__ gN, const float* __restrict__ bN,
    const float* __restrict__ gT, const float* __restrict__ bT)
{
    const int w = threadIdx.x >> 5, l = threadIdx.x & 31;
    const int row0 = blockIdx.x * 8 + w;
    const __half *src; const float *gamma, *beta; int hoff, row;
    if (row0 < MTOK) { src = d_preN; gamma = gN; beta = bN; hoff = 0;    row = row0; }
    else             { src = d_preT; gamma = gT; beta = bT; hoff = HDIM; row = row0 - MTOK; }
    const uint4* x = (const uint4*)(src + (size_t)row * HDIM);
    float f[4][8];
    float s = 0.f;
    #pragma unroll
    for (int i = 0; i < 4; i++) {
        uint4 raw = x[i*32 + l];
        unpack8(raw, f[i]);
        #pragma unroll
        for (int j = 0; j < 8; j++) s += f[i][j];
    }
    s = warpSum(s);
    float mu = s * (1.f / HDIM);
    float sq = 0.f;
    #pragma unroll
    for (int i = 0; i < 4; i++)
        #pragma unroll
        for (int j = 0; j < 8; j++) { float d = f[i][j] - mu; sq += d*d; }
    sq = warpSum(sq);
    float inv = rsqrtf(sq * (1.f / HDIM) + 1e-5f);
    uint4* dh = (uint4*)(d_actH + (size_t)row * (2*HDIM) + hoff);
    const float4* g4 = (const float4*)gamma;
    const float4* b4 = (const float4*)beta;
    #pragma unroll
    for (int i = 0; i < 4; i++) {
        int e = (i*32 + l) * 2;
        float o[8];
        #pragma unroll
        for (int h = 0; h < 2; h++) {
            float4 g = g4[e + h], b = b4[e + h];
            o[h*4+0] = fmaxf((f[i][h*4+0]-mu)*inv*g.x + b.x, 0.f);
            o[h*4+1] = fmaxf((f[i][h*4+1]-mu)*inv*g.y + b.y, 0.f);
            o[h*4+2] = fmaxf((f[i][h*4+2]-mu)*inv*g.z + b.z, 0.f);
            o[h*4+3] = fmaxf((f[i][h*4+3]-mu)*inv*g.w + b.w, 0.f);
        }
        uint4 ov;
        *(__half2*)&ov.x = __floats2half2_rn(o[0], o[1]);
        *(__half2*)&ov.y = __floats2half2_rn(o[2], o[3]);
        *(__half2*)&ov.z = __floats2half2_rn(o[4], o[5]);
        *(__half2*)&ov.w = __floats2half2_rn(o[6], o[7]);
        dh[i*32 + l] = ov;
    }
}

// ---------------- final: warp-per-row. LN+ReLU(hidH fp16)->Wg2->sigmoid->gate actH ----
__global__ void __launch_bounds__(256) k_gate_finish(
    const float* __restrict__ gg, const float* __restrict__ bgv,
    const float* __restrict__ Wg2, const float* __restrict__ bg2,
    float* __restrict__ out)
{
    const int w = threadIdx.x >> 5, l = threadIdx.x & 31;
    const int row  = blockIdx.x * 8 + w;
    const int lang = d_lang[row >> 9];
    const uint4* x = (const uint4*)(d_hidH + (size_t)row * HDIM);
    float f[4][8];
    float s = 0.f;
    #pragma unroll
    for (int i = 0; i < 4; i++) {
        uint4 raw = x[i*32 + l];
        unpack8(raw, f[i]);
        #pragma unroll
        for (int j = 0; j < 8; j++) s += f[i][j];
    }
    s = warpSum(s);
    float mu = s * (1.f / HDIM);
    float sq = 0.f;
    #pragma unroll
    for (int i = 0; i < 4; i++)
        #pragma unroll
        for (int j = 0; j < 8; j++) { float d = f[i][j] - mu; sq += d*d; }
    sq = warpSum(sq);
    float inv = rsqrtf(sq * (1.f / HDIM) + 1e-5f);

    const float4* g4 = (const float4*)(gg  + (size_t)lang * HDIM);
    const float4* b4 = (const float4*)(bgv + (size_t)lang * HDIM);
    const float4* w4 = (const float4*)(Wg2 + (size_t)lang * HDIM * 2);
    float s0 = 0.f, s1 = 0.f;
    #pragma unroll
    for (int i = 0; i < 4; i++) {
        int e = (i*32 + l) * 2;
        #pragma unroll
        for (int h = 0; h < 2; h++) {
            float4 g = g4[e + h], b = b4[e + h];
            float h0 = fmaxf((f[i][h*4+0]-mu)*inv*g.x + b.x, 0.f);
            float h1 = fmaxf((f[i][h*4+1]-mu)*inv*g.y + b.y, 0.f);
            float h2 = fmaxf((f[i][h*4+2]-mu)*inv*g.z + b.z, 0.f);
            float h3 = fmaxf((f[i][h*4+3]-mu)*inv*g.w + b.w, 0.f);
            float4 wa = w4[(e + h)*2], wb = w4[(e + h)*2 + 1];
            s0 += h0*wa.x + h1*wa.z + h2*wb.x + h3*wb.z;
            s1 += h0*wa.y + h1*wa.w + h2*wb.y + h3*wb.w;
        }
    }
    s0 = warpSum(s0);
    s1 = warpSum(s1);
    float g0 = 1.f / (1.f + expf(-(s0 + bg2[lang*2 + 0])));
    float g1 = 1.f / (1.f + expf(-(s1 + bg2[lang*2 + 1])));

    const uint4* an = (const uint4*)(d_actH + (size_t)row * (2*HDIM));
    const uint4* at = (const uint4*)(d_actH + (size_t)row * (2*HDIM) + HDIM);
    float4* o0 = (float4*)(out + (size_t)row * HDIM);
    float4* o1 = (float4*)(out + (size_t)MTOK * HDIM + (size_t)row * HDIM);
    #pragma unroll
    for (int i = 0; i < 4; i++) {
        int idx = i*32 + l;
        float na[8], ta[8];
        unpack8(an[idx], na);
        unpack8(at[idx], ta);
        o0[idx*2]   = make_float4(na[0]*g0, na[1]*g0, na[2]*g0, na[3]*g0);
        o0[idx*2+1] = make_float4(na[4]*g0, na[5]*g0, na[6]*g0, na[7]*g0);
        o1[idx*2]   = make_float4(ta[0]*g1, ta[1]*g1, ta[2]*g1, ta[3]*g1);
        o1[idx*2+1] = make_float4(ta[4]*g1, ta[5]*g1, ta[6]*g1, ta[7]*g1);
    }
}

extern "C" void kernel_launch(void* const* d_in, const int* in_sizes, int n_in,
                              void* d_out, int out_size)
{
    const float* ner    = (const float*)d_in[0];
    const float* topf   = (const float*)d_in[1];
    const int*   lang   = (const int*)d_in[2];
    const float* W_ner  = (const float*)d_in[3];
    const float* b_ner  = (const float*)d_in[4];
    const float* g_ner  = (const float*)d_in[5];
    const float* be_ner = (const float*)d_in[6];
    const float* W_top  = (const float*)d_in[7];
    const float* b_top  = (const float*)d_in[8];
    const float* g_top  = (const float*)d_in[9];
    const float* be_top = (const float*)d_in[10];
    const float* Wg1    = (const float*)d_in[11];
    const float* bg1    = (const float*)d_in[12];
    const float* gg     = (const float*)d_in[13];
    const float* bg     = (const float*)d_in[14];
    const float* Wg2    = (const float*)d_in[15];
    const float* bg2    = (const float*)d_in[16];
    float* out = (float*)d_out;

    __half *pNerH, *pTopH, *pWner, *pWtop, *pWg1, *pActH, *pPreN, *pPreT, *pHidH;
    cudaGetSymbolAddress((void**)&pNerH, d_nerH);
    cudaGetSymbolAddress((void**)&pTopH, d_topH);
    cudaGetSymbolAddress((void**)&pWner, d_WnerH);
    cudaGetSymbolAddress((void**)&pWtop, d_WtopH);
    cudaGetSymbolAddress((void**)&pWg1,  d_Wg1H);
    cudaGetSymbolAddress((void**)&pActH, d_actH);
    cudaGetSymbolAddress((void**)&pPreN, d_preN);
    cudaGetSymbolAddress((void**)&pPreT, d_preT);
    cudaGetSymbolAddress((void**)&pHidH, d_hidH);

    static bool attr_done = false;
    if (!attr_done) {
        cudaFuncSetAttribute(k_mm_fp16<12,false,true>, cudaFuncAttributeMaxDynamicSharedMemorySize, SMEM_MM);
        cudaFuncSetAttribute(k_mm_fp16<32,true,false>, cudaFuncAttributeMaxDynamicSharedMemorySize, SMEM_MM);
        attr_done = true;
    }

    // serial prefix: decode + convert features + shared weights (NOT Wg1)
    k_prep0<<<PREP0_GRID, 256>>>(ner, topf, W_ner, W_top, lang);

    // shared transforms: combined z=2 launch (R12 structure) + 256 converter CTAs
    // converting Wg1 in the GEMM's DRAM shadow (consumer = gate GEMM, next launch+1)
    k_mm_fp16<12,false,true><<<dim3(HDIM/128, YMAIN + YCONV, 2), 256, SMEM_MM>>>(
        pNerH, pTopH, pWner, pWtop, b_ner, b_top, pPreN, pPreT,
        Wg1, pWg1, R_WG1);

    k_ln_relu2<<<2*MTOK/8, 256>>>(g_ner, be_ner, g_top, be_top);

    // gate MLP (K=2048), per-batch language selected
    k_mm_fp16<32,true,false><<<dim3(HDIM/128, YMAIN, 1), 256, SMEM_MM>>>(
        pActH, nullptr, pWg1, nullptr, bg1, nullptr, pHidH, nullptr,
        nullptr, nullptr, 0);

    k_gate_finish<<<MTOK/8, 256>>>(gg, bg, Wg2, bg2, out);
}